// round 1
// baseline (speedup 1.0000x reference)
#include <cuda_runtime.h>

// Block-diagonal grouped conv2d: 64 groups, 4 in-ch -> 4 out-ch per group, 3x3, pad 1.
// x:   (32, 256, 128, 128) fp32, channel index = ci*64 + head
// w:   (64, 4, 4, 3, 3)          w[head][co][ci][ky][kx]
// b:   (64, 4)
// out: (32, 256, 128, 128) fp32, channel index = co*64 + head
//
// Strategy: smem-tiled, packed f32x2 FMA (Blackwell FFMA2) for 2x fp32 rate.

#define TY 16
#define SROWS (TY + 2)
#define SCOLS 132          // 130 used (halo cols), padded
#define THREADS 256
#define H 128
#define W 128
#define PLANE (H * W)

typedef unsigned long long u64;

__device__ __forceinline__ u64 pk(float lo, float hi) {
    u64 r; asm("mov.b64 %0, {%1, %2};" : "=l"(r) : "f"(lo), "f"(hi)); return r;
}
__device__ __forceinline__ void upk(u64 v, float &lo, float &hi) {
    asm("mov.b64 {%0, %1}, %2;" : "=f"(lo), "=f"(hi) : "l"(v));
}
// d = a*b + d  (packed 2x fp32)
__device__ __forceinline__ void ffma2(u64 &d, u64 a, u64 b) {
    asm("fma.rn.f32x2 %0, %1, %2, %0;" : "+l"(d) : "l"(a), "l"(b));
}

__global__ __launch_bounds__(THREADS, 2)
void bdconv_kernel(const float* __restrict__ x, const float* __restrict__ w,
                   const float* __restrict__ bias, float* __restrict__ out) {
    __shared__ float s_in[4 * SROWS * SCOLS];
    __shared__ u64   s_w[4 * 3 * 3 * 4];   // [ci][ky][kx][co], value duplicated in both halves
    __shared__ float s_bias[4];

    const int blk  = blockIdx.x;
    const int tile = blk & 7;          // 8 row-tiles of 16
    const int head = (blk >> 3) & 63;
    const int b    = blk >> 9;
    const int y0   = tile * TY;
    const int tid  = threadIdx.x;

    // ---- stage weights (duplicated into f32x2 lanes) + bias ----
    if (tid < 144) {
        const int co = tid / 36;
        const int rem = tid % 36;
        const int ci = rem / 9;
        const int t  = rem % 9;        // ky*3+kx
        const float wv = w[((head * 4 + co) * 4 + ci) * 9 + t];
        s_w[(ci * 9 + t) * 4 + co] = pk(wv, wv);
    }
    if (tid < 4) s_bias[tid] = bias[head * 4 + tid];

    // ---- stage input tile with halo (zero-padded) ----
    const float* xb = x + ((long long)b * 256 + head) * PLANE;  // ci stride = 64*PLANE
    #pragma unroll 1
    for (int idx = tid; idx < 4 * SROWS * SCOLS; idx += THREADS) {
        const int ci  = idx / (SROWS * SCOLS);
        const int rem = idx - ci * (SROWS * SCOLS);
        const int r   = rem / SCOLS;
        const int c   = rem - r * SCOLS;
        const int y   = y0 - 1 + r;
        const int xx  = c - 1;
        float v = 0.0f;
        if (y >= 0 && y < H && xx >= 0 && xx < W)
            v = __ldg(xb + ci * (64 * PLANE) + y * W + xx);
        s_in[idx] = v;
    }
    __syncthreads();

    // ---- compute: each thread = 8 pixels x 4 out-channels (16 f32x2 accumulators) ----
    const int r  = tid >> 4;           // row within tile, 0..15
    const int xq = (tid & 15) << 3;    // pixel start, 0..120 step 8

    u64 acc[4][4];                     // [co][pixel-pair]
    #pragma unroll
    for (int co = 0; co < 4; co++) {
        const float bv = s_bias[co];
        const u64 bp = pk(bv, bv);
        #pragma unroll
        for (int q = 0; q < 4; q++) acc[co][q] = bp;
    }

    #pragma unroll
    for (int ci = 0; ci < 4; ci++) {
        const float* plane = s_in + ci * (SROWS * SCOLS);
        #pragma unroll
        for (int ky = 0; ky < 3; ky++) {
            const float* row = plane + (r + ky) * SCOLS + xq;
            // 10-wide sliding window (pixels xq-1 .. xq+8 in input coords)
            float v[10];
            #pragma unroll
            for (int i = 0; i < 10; i++) v[i] = row[i];
            // all 9 adjacent pairs (both parities)
            u64 p[9];
            #pragma unroll
            for (int s = 0; s < 9; s++) p[s] = pk(v[s], v[s + 1]);
            // weights for this (ci, ky): [kx][co], broadcast from smem
            u64 wr[3][4];
            #pragma unroll
            for (int kx = 0; kx < 3; kx++)
                #pragma unroll
                for (int co = 0; co < 4; co++)
                    wr[kx][co] = s_w[(ci * 9 + ky * 3 + kx) * 4 + co];
            // 48 packed FMAs
            #pragma unroll
            for (int q = 0; q < 4; q++)
                #pragma unroll
                for (int kx = 0; kx < 3; kx++) {
                    const u64 in = p[2 * q + kx];
                    #pragma unroll
                    for (int co = 0; co < 4; co++)
                        ffma2(acc[co][q], wr[kx][co], in);
                }
        }
    }

    // ---- store: coalesced float4 writes ----
    const int y = y0 + r;
    #pragma unroll
    for (int co = 0; co < 4; co++) {
        float o[8];
        #pragma unroll
        for (int q = 0; q < 4; q++) upk(acc[co][q], o[2 * q], o[2 * q + 1]);
        float4* dst = (float4*)(out + (((long long)(b * 256 + co * 64 + head)) * H + y) * W + xq);
        dst[0] = make_float4(o[0], o[1], o[2], o[3]);
        dst[1] = make_float4(o[4], o[5], o[6], o[7]);
    }
}

extern "C" void kernel_launch(void* const* d_in, const int* in_sizes, int n_in,
                              void* d_out, int out_size) {
    const float* x    = (const float*)d_in[0];
    const float* w    = (const float*)d_in[1];
    const float* bias = (const float*)d_in[2];
    float* out        = (float*)d_out;
    (void)in_sizes; (void)n_in; (void)out_size;
    bdconv_kernel<<<32 * 64 * 8, THREADS>>>(x, w, bias, out);
}

// round 2
// speedup vs baseline: 4.2120x; 4.2120x over previous
#include <cuda_runtime.h>

// Block-diagonal grouped conv2d: 64 groups, 4 in-ch -> 4 out-ch per group, 3x3, pad 1.
// x:   (32, 256, 128, 128) fp32, channel index = ci*64 + head
// w:   (64, 4, 4, 3, 3)          w[head][co][ci][ky][kx]
// b:   (64, 4)
// out: (32, 256, 128, 128) fp32, channel index = co*64 + head
//
// v2: packed f32x2 FMA + wide LDS window (2xLDS.128+LDS.32) + 3 CTAs/SM.

#define TY 16
#define SROWS (TY + 2)
#define SCOLS 136          // 4 halo + 128 interior + 4 halo; x -> col = x + 4
#define THREADS 256
#define H 128
#define W 128
#define PLANE (H * W)

typedef unsigned long long u64;

__device__ __forceinline__ u64 pk(float lo, float hi) {
    u64 r; asm("mov.b64 %0, {%1, %2};" : "=l"(r) : "f"(lo), "f"(hi)); return r;
}
__device__ __forceinline__ void upk(u64 v, float &lo, float &hi) {
    asm("mov.b64 {%0, %1}, %2;" : "=f"(lo), "=f"(hi) : "l"(v));
}
// d += a*b  (packed 2x fp32)
__device__ __forceinline__ void ffma2(u64 &d, u64 a, u64 b) {
    asm("fma.rn.f32x2 %0, %1, %2, %0;" : "+l"(d) : "l"(a), "l"(b));
}

__global__ __launch_bounds__(THREADS, 3)
void bdconv_kernel(const float* __restrict__ x, const float* __restrict__ w,
                   const float* __restrict__ bias, float* __restrict__ out) {
    __shared__ float s_in[4 * SROWS * SCOLS];   // [ci][r][c], c = x+4
    __shared__ u64   s_w[4 * 3 * 3 * 4];        // [ci][ky][kx][co], duplicated halves
    __shared__ float s_bias[4];

    const int blk  = blockIdx.x;
    const int tile = blk & 7;          // 8 row-tiles of 16
    const int head = (blk >> 3) & 63;
    const int b    = blk >> 9;
    const int y0   = tile * TY;
    const int tid  = threadIdx.x;
    const int wrp  = tid >> 5;
    const int lane = tid & 31;

    // ---- stage weights (duplicated into f32x2 lanes) + bias ----
    if (tid < 144) {
        const int co  = tid / 36;
        const int rem = tid % 36;
        const int ci  = rem / 9;
        const int t   = rem % 9;       // ky*3+kx
        const float wv = w[((head * 4 + co) * 4 + ci) * 9 + t];
        s_w[(ci * 9 + t) * 4 + co] = pk(wv, wv);
    }
    if (tid < 4) s_bias[tid] = bias[head * 4 + tid];

    // ---- zero halo columns (x=-1..-4 and x=128..131 are always out of range) ----
    // 72 rows x 8 halo cols = 576 floats
    for (int idx = tid; idx < 72 * 8; idx += THREADS) {
        const int row = idx >> 3;
        const int h8  = idx & 7;
        const int c   = (h8 < 4) ? h8 : (128 + h8);
        s_in[row * SCOLS + c] = 0.0f;
    }

    // ---- stage interior: warp per row, float4 coalesced ----
    const float* xb = x + ((long long)b * 256 + head) * PLANE;  // ci stride = 64*PLANE
    #pragma unroll
    for (int k = 0; k < 9; k++) {                 // 72 rows / 8 warps
        const int rr = wrp + (k << 3);            // 0..71
        const int ci = rr / SROWS;
        const int r  = rr - ci * SROWS;
        const int y  = y0 - 1 + r;
        float4 v = make_float4(0.f, 0.f, 0.f, 0.f);
        if (y >= 0 && y < H)
            v = *(const float4*)(xb + ci * (64 * PLANE) + y * W + (lane << 2));
        *(float4*)(s_in + rr * SCOLS + 4 + (lane << 2)) = v;
    }
    __syncthreads();

    // ---- compute: each thread = 8 pixels x 4 out-channels (16 f32x2 accumulators) ----
    const int r  = tid >> 4;           // row within tile, 0..15
    const int xq = (tid & 15) << 3;    // pixel start, 0..120 step 8

    u64 acc[4][4];                     // [co][pixel-pair]
    #pragma unroll
    for (int co = 0; co < 4; co++) {
        const float bv = s_bias[co];
        const u64 bp = pk(bv, bv);
        #pragma unroll
        for (int q = 0; q < 4; q++) acc[co][q] = bp;
    }

    // window base: col xq covers x = xq-4..xq-1 (A), xq+4 -> x=xq..xq+3 (B),
    // xq+8 -> x=xq+4..xq+7 (C), scalar at col xq+12 -> x=xq+8 (D)
    const float* rbase = s_in + r * SCOLS + xq;

    #pragma unroll
    for (int ci = 0; ci < 4; ci++) {
        const float* plane = rbase + ci * (SROWS * SCOLS);
        #pragma unroll
        for (int ky = 0; ky < 3; ky++) {
            const float* rp = plane + ky * SCOLS;
            const float4 A = *(const float4*)(rp);
            const float4 B = *(const float4*)(rp + 4);
            const float4 C = *(const float4*)(rp + 8);
            const float  D = rp[12];
            // 9 adjacent pairs of the 10-value window x(xq-1 .. xq+8)
            u64 p[9];
            p[0] = pk(A.w, B.x);
            p[1] = pk(B.x, B.y);
            p[2] = pk(B.y, B.z);
            p[3] = pk(B.z, B.w);
            p[4] = pk(B.w, C.x);
            p[5] = pk(C.x, C.y);
            p[6] = pk(C.y, C.z);
            p[7] = pk(C.z, C.w);
            p[8] = pk(C.w, D);
            // weights for this (ci, ky): [kx][co], broadcast from smem
            const u64* wb = s_w + (ci * 9 + ky * 3) * 4;
            u64 wr[3][4];
            #pragma unroll
            for (int kx = 0; kx < 3; kx++)
                #pragma unroll
                for (int co = 0; co < 4; co++)
                    wr[kx][co] = wb[kx * 4 + co];
            // 48 packed FMAs
            #pragma unroll
            for (int q = 0; q < 4; q++)
                #pragma unroll
                for (int kx = 0; kx < 3; kx++) {
                    const u64 in = p[2 * q + kx];
                    #pragma unroll
                    for (int co = 0; co < 4; co++)
                        ffma2(acc[co][q], wr[kx][co], in);
                }
        }
    }

    // ---- store: coalesced float4 writes ----
    const int y = y0 + r;
    #pragma unroll
    for (int co = 0; co < 4; co++) {
        float o[8];
        #pragma unroll
        for (int q = 0; q < 4; q++) upk(acc[co][q], o[2 * q], o[2 * q + 1]);
        float4* dst = (float4*)(out + (((long long)(b * 256 + co * 64 + head)) * H + y) * W + xq);
        dst[0] = make_float4(o[0], o[1], o[2], o[3]);
        dst[1] = make_float4(o[4], o[5], o[6], o[7]);
    }
}

extern "C" void kernel_launch(void* const* d_in, const int* in_sizes, int n_in,
                              void* d_out, int out_size) {
    const float* x    = (const float*)d_in[0];
    const float* w    = (const float*)d_in[1];
    const float* bias = (const float*)d_in[2];
    float* out        = (float*)d_out;
    (void)in_sizes; (void)n_in; (void)out_size;
    bdconv_kernel<<<32 * 64 * 8, THREADS>>>(x, w, bias, out);
}

// round 3
// speedup vs baseline: 4.5884x; 1.0894x over previous
#include <cuda_runtime.h>

// Block-diagonal grouped conv2d: 64 groups, 4 in-ch -> 4 out-ch per group, 3x3, pad 1.
// x:   (32, 256, 128, 128) fp32, channel index = ci*64 + head
// w:   (64, 4, 4, 3, 3)          w[head][co][ci][ky][kx]
// b:   (64, 4)
// out: (32, 256, 128, 128) fp32, channel index = co*64 + head
//
// v3: padded smem layout (conflict-free), LDS.128 weights, f32x2 FMA, 3 CTAs/SM.

#define TY 16
#define SROWS (TY + 2)
#define SROW_P 152               // padded physical row stride (floats)
#define PLANE_P (SROWS * SROW_P) // 2736
#define THREADS 256
#define H 128
#define W 128
#define PLANE (H * W)

// logical col c (0..135, x = c-4) -> physical col: +4 pad floats per 32-col group
#define PCOL(c) ((c) + 4 * ((c) >> 5))

typedef unsigned long long u64;

__device__ __forceinline__ u64 pk(float lo, float hi) {
    u64 r; asm("mov.b64 %0, {%1, %2};" : "=l"(r) : "f"(lo), "f"(hi)); return r;
}
// d += a*b  (packed 2x fp32)
__device__ __forceinline__ void ffma2(u64 &d, u64 a, u64 b) {
    asm("fma.rn.f32x2 %0, %1, %2, %0;" : "+l"(d) : "l"(a), "l"(b));
}

union F4 {
    float4 f;
    ulonglong2 u;
};

__global__ __launch_bounds__(THREADS, 3)
void bdconv_kernel(const float* __restrict__ x, const float* __restrict__ w,
                   const float* __restrict__ bias, float* __restrict__ out) {
    __shared__ __align__(16) float s_in[4 * PLANE_P];      // [ci][r][pcol]
    __shared__ __align__(16) u64   s_w[4 * 3 * 3 * 4];     // [ci][ky][kx][co] dup halves
    __shared__ float s_bias[4];

    const int blk  = blockIdx.x;
    const int tile = blk & 7;          // 8 row-tiles of 16
    const int head = (blk >> 3) & 63;
    const int b    = blk >> 9;
    const int y0   = tile * TY;
    const int tid  = threadIdx.x;
    const int wrp  = tid >> 5;
    const int lane = tid & 31;

    // ---- stage weights (duplicated into f32x2 lanes) + bias ----
    if (tid < 144) {
        const int co  = tid / 36;
        const int rem = tid % 36;
        const int ci  = rem / 9;
        const int t   = rem % 9;       // ky*3+kx
        const float wv = w[((head * 4 + co) * 4 + ci) * 9 + t];
        s_w[(ci * 9 + t) * 4 + co] = pk(wv, wv);
    }
    if (tid < 4) s_bias[tid] = bias[head * 4 + tid];

    // ---- zero halo columns (logical cols 0..3 and 132..135) ----
    for (int idx = tid; idx < 72 * 8; idx += THREADS) {
        const int row = idx >> 3;                 // 0..71 = ci*18 + r
        const int h8  = idx & 7;
        const int pc  = (h8 < 4) ? h8 : (144 + h8);   // PCOL: 0..3, 148..151
        s_in[row * SROW_P + pc] = 0.0f;
    }

    // ---- stage interior: warp per row, float4 coalesced ----
    const float* xb = x + ((long long)b * 256 + head) * PLANE;  // ci stride = 64*PLANE
    const int cst = 4 + (lane << 2);              // logical col 4..131
    const int pst = PCOL(cst);
    #pragma unroll
    for (int k = 0; k < 9; k++) {                 // 72 rows / 8 warps
        const int rr = wrp + (k << 3);            // 0..71
        const int ci = rr / SROWS;
        const int r  = rr - ci * SROWS;
        const int y  = y0 - 1 + r;
        float4 v = make_float4(0.f, 0.f, 0.f, 0.f);
        if (y >= 0 && y < H)
            v = *(const float4*)(xb + ci * (64 * PLANE) + y * W + (lane << 2));
        *(float4*)(s_in + rr * SROW_P + pst) = v;
    }
    __syncthreads();

    // ---- compute: each thread = 8 pixels x 4 out-channels ----
    const int r  = tid >> 4;           // row within tile, 0..15
    const int xq = (tid & 15) << 3;    // pixel start, 0..120 step 8

    // per-thread physical base offsets (window cols xq+3 .. xq+12)
    const int rb  = r * SROW_P;
    const int pB  = rb + PCOL(xq + 4);   // float4: x = xq..xq+3
    const int pC  = rb + PCOL(xq + 8);   // float4: x = xq+4..xq+7
    const int pA  = rb + PCOL(xq + 3);   // scalar: x = xq-1
    const int pD  = rb + PCOL(xq + 12);  // scalar: x = xq+8

    u64 acc[4][4];                     // [co][pixel-pair]
    #pragma unroll
    for (int co = 0; co < 4; co++) {
        const float bv = s_bias[co];
        const u64 bp = pk(bv, bv);
        #pragma unroll
        for (int q = 0; q < 4; q++) acc[co][q] = bp;
    }

    #pragma unroll
    for (int ci = 0; ci < 4; ci++) {
        #pragma unroll
        for (int ky = 0; ky < 3; ky++) {
            const int base = ci * PLANE_P + ky * SROW_P;   // compile-time constant
            F4 B, C;
            B.f = *(const float4*)(s_in + base + pB);
            C.f = *(const float4*)(s_in + base + pC);
            const float aw = s_in[base + pA];
            const float dd = s_in[base + pD];

            // 9 adjacent pairs of window x(xq-1 .. xq+8); aligned ones free via union
            u64 p[9];
            p[0] = pk(aw,    B.f.x);
            p[1] = B.u.x;
            p[2] = pk(B.f.y, B.f.z);
            p[3] = B.u.y;
            p[4] = pk(B.f.w, C.f.x);
            p[5] = C.u.x;
            p[6] = pk(C.f.y, C.f.z);
            p[7] = C.u.y;
            p[8] = pk(C.f.w, dd);

            // weights: 6 x LDS.128 broadcast -> [kx][co]
            const ulonglong2* wp = (const ulonglong2*)(s_w + (ci * 9 + ky * 3) * 4);
            ulonglong2 wv[6];
            #pragma unroll
            for (int j = 0; j < 6; j++) wv[j] = wp[j];

            // 48 packed FMAs
            #pragma unroll
            for (int q = 0; q < 4; q++)
                #pragma unroll
                for (int kx = 0; kx < 3; kx++) {
                    const u64 in = p[2 * q + kx];
                    ffma2(acc[0][q], wv[kx * 2 + 0].x, in);
                    ffma2(acc[1][q], wv[kx * 2 + 0].y, in);
                    ffma2(acc[2][q], wv[kx * 2 + 1].x, in);
                    ffma2(acc[3][q], wv[kx * 2 + 1].y, in);
                }
        }
    }

    // ---- store: coalesced 2x STG.128 per co, no unpack movs ----
    const int y = y0 + r;
    #pragma unroll
    for (int co = 0; co < 4; co++) {
        ulonglong2* dst = (ulonglong2*)(out +
            (((long long)(b * 256 + co * 64 + head)) * H + y) * W + xq);
        ulonglong2 s0, s1;
        s0.x = acc[co][0]; s0.y = acc[co][1];
        s1.x = acc[co][2]; s1.y = acc[co][3];
        dst[0] = s0;
        dst[1] = s1;
    }
}

extern "C" void kernel_launch(void* const* d_in, const int* in_sizes, int n_in,
                              void* d_out, int out_size) {
    const float* x    = (const float*)d_in[0];
    const float* w    = (const float*)d_in[1];
    const float* bias = (const float*)d_in[2];
    float* out        = (float*)d_out;
    (void)in_sizes; (void)n_in; (void)out_size;
    bdconv_kernel<<<32 * 64 * 8, THREADS>>>(x, w, bias, out);
}

// round 4
// speedup vs baseline: 4.6038x; 1.0034x over previous
#include <cuda_runtime.h>

// Block-diagonal grouped conv2d: 64 groups, 4 in-ch -> 4 out-ch per group, 3x3, pad 1.
// x:   (32, 256, 128, 128) fp32, channel index = ci*64 + head
// w:   (64, 4, 4, 3, 3)          w[head][co][ci][ky][kx]
// b:   (64, 4)
// out: (32, 256, 128, 128) fp32, channel index = co*64 + head
//
// v4: chunk-swizzled smem phys(c)=c+4*(c>>3) -> all vector LDS conflict-free;
//     window edges via warp shuffle (no scalar LDS); conflict-free staging;
//     packed f32x2 FMA; dynamic smem, 3 CTAs/SM.

#define TY 16
#define SROW_P 188                   // phys floats per row: phys(127)=187
#define PLANE_P (18 * SROW_P)        // 3384
#define S_IN_FLOATS (4 * PLANE_P)    // 13536
#define THREADS 256
#define H 128
#define W 128
#define PLANE (H * W)
#define SMEM_BYTES ((S_IN_FLOATS + 2 * 144 + 4) * 4)

typedef unsigned long long u64;

__device__ __forceinline__ u64 pk(float lo, float hi) {
    u64 r; asm("mov.b64 %0, {%1, %2};" : "=l"(r) : "f"(lo), "f"(hi)); return r;
}
// d += a*b  (packed 2x fp32)
__device__ __forceinline__ void ffma2(u64 &d, u64 a, u64 b) {
    asm("fma.rn.f32x2 %0, %1, %2, %0;" : "+l"(d) : "l"(a), "l"(b));
}

union F4 {
    float4 f;
    ulonglong2 u;
};

__global__ __launch_bounds__(THREADS, 3)
void bdconv_kernel(const float* __restrict__ x, const float* __restrict__ w,
                   const float* __restrict__ bias, float* __restrict__ out) {
    extern __shared__ __align__(16) float smem[];
    float* s_in   = smem;                       // [ci][r][phys-col]
    u64*   s_w    = (u64*)(smem + S_IN_FLOATS); // [ci][ky][kx][co], dup halves
    float* s_bias = (float*)(s_w + 144);

    const int blk  = blockIdx.x;
    const int tile = blk & 7;          // 8 row-tiles of 16
    const int head = (blk >> 3) & 63;
    const int b    = blk >> 9;
    const int y0   = tile * TY;
    const int tid  = threadIdx.x;
    const int wrp  = tid >> 5;
    const int lane = tid & 31;

    // ---- stage weights (duplicated into f32x2 lanes) + bias ----
    if (tid < 144) {
        const int co  = tid / 36;
        const int rem = tid % 36;
        const int ci  = rem / 9;
        const int t   = rem % 9;       // ky*3+kx
        const float wv = w[((head * 4 + co) * 4 + ci) * 9 + t];
        s_w[(ci * 9 + t) * 4 + co] = pk(wv, wv);
    }
    if (tid < 4) s_bias[tid] = bias[head * 4 + tid];

    // ---- stage input: 2 warps per ci-plane, 9 rows per warp ----
    // lane->chunk permutation keeps STS.128 conflict-free under the swizzle:
    //   lanes 0-15  -> even chunks h=2l   (phys chunk sigma=3l)
    //   lanes 16-31 -> odd  chunks h=2m+1 (phys chunk sigma=3m+1), m=l-16
    const int ci_s = wrp >> 1;
    const int r0s  = (wrp & 1) * 9;
    int x0, sig;
    if (lane < 16) { x0 = lane << 3;            sig = 3 * lane; }
    else           { x0 = ((lane - 16) << 3) + 4; sig = 3 * (lane - 16) + 1; }
    const float* xpl = x + ((long long)b * 256 + head) * PLANE + ci_s * (64 * PLANE);
    float* spl = s_in + ci_s * PLANE_P + (sig << 2);
    #pragma unroll
    for (int k = 0; k < 9; k++) {
        const int r = r0s + k;
        const int y = y0 - 1 + r;
        float4 v = make_float4(0.f, 0.f, 0.f, 0.f);
        if (y >= 0 && y < H)
            v = *(const float4*)(xpl + y * W + x0);
        *(float4*)(spl + r * SROW_P) = v;
    }
    __syncthreads();

    // ---- compute: each thread = 8 pixels x 4 out-channels ----
    const int r  = tid >> 4;           // row within tile, 0..15
    const int j  = tid & 15;           // pixel-octet index, x = 8j..8j+7
    // phys(8j) = 12j ; B covers x=8j..8j+3, C (at +4 floats) covers x=8j+4..8j+7
    const int base = r * SROW_P + 12 * j;

    u64 acc[4][4];                     // [co][pixel-pair]
    #pragma unroll
    for (int co = 0; co < 4; co++) {
        const float bv = s_bias[co];
        const u64 bp = pk(bv, bv);
        #pragma unroll
        for (int q = 0; q < 4; q++) acc[co][q] = bp;
    }

    #pragma unroll
    for (int ci = 0; ci < 4; ci++) {
        #pragma unroll
        for (int ky = 0; ky < 3; ky++) {
            const int imm = ci * PLANE_P + ky * SROW_P;   // compile-time
            F4 B, C;
            B.f = *(const float4*)(s_in + imm + base);
            C.f = *(const float4*)(s_in + imm + base + 4);

            // window edges from neighbor lanes (zero-pad at tile row ends)
            float A = __shfl_up_sync(0xffffffffu, C.f.w, 1);
            float D = __shfl_down_sync(0xffffffffu, B.f.x, 1);
            if (j == 0)  A = 0.0f;
            if (j == 15) D = 0.0f;

            // 9 adjacent pairs of window x(8j-1 .. 8j+8)
            u64 p[9];
            p[0] = pk(A,     B.f.x);
            p[1] = B.u.x;
            p[2] = pk(B.f.y, B.f.z);
            p[3] = B.u.y;
            p[4] = pk(B.f.w, C.f.x);
            p[5] = C.u.x;
            p[6] = pk(C.f.y, C.f.z);
            p[7] = C.u.y;
            p[8] = pk(C.f.w, D);

            // weights: 6 x LDS.128 uniform broadcast -> [kx][co]
            const ulonglong2* wp = (const ulonglong2*)(s_w + (ci * 9 + ky * 3) * 4);
            ulonglong2 wv[6];
            #pragma unroll
            for (int t = 0; t < 6; t++) wv[t] = wp[t];

            // 48 packed FMAs
            #pragma unroll
            for (int q = 0; q < 4; q++)
                #pragma unroll
                for (int kx = 0; kx < 3; kx++) {
                    const u64 in = p[2 * q + kx];
                    ffma2(acc[0][q], wv[kx * 2 + 0].x, in);
                    ffma2(acc[1][q], wv[kx * 2 + 0].y, in);
                    ffma2(acc[2][q], wv[kx * 2 + 1].x, in);
                    ffma2(acc[3][q], wv[kx * 2 + 1].y, in);
                }
        }
    }

    // ---- store: coalesced 2x STG.128 per co ----
    const int y = y0 + r;
    float* obase = out + (((long long)b * 256 + head) * H + y) * W + (j << 3);
    #pragma unroll
    for (int co = 0; co < 4; co++) {
        ulonglong2* dst = (ulonglong2*)(obase + (long long)co * (64 * PLANE));
        ulonglong2 s0, s1;
        s0.x = acc[co][0]; s0.y = acc[co][1];
        s1.x = acc[co][2]; s1.y = acc[co][3];
        dst[0] = s0;
        dst[1] = s1;
    }
}

extern "C" void kernel_launch(void* const* d_in, const int* in_sizes, int n_in,
                              void* d_out, int out_size) {
    const float* x    = (const float*)d_in[0];
    const float* w    = (const float*)d_in[1];
    const float* bias = (const float*)d_in[2];
    float* out        = (float*)d_out;
    (void)in_sizes; (void)n_in; (void)out_size;
    cudaFuncSetAttribute(bdconv_kernel,
                         cudaFuncAttributeMaxDynamicSharedMemorySize, SMEM_BYTES);
    bdconv_kernel<<<32 * 64 * 8, THREADS, SMEM_BYTES>>>(x, w, bias, out);
}